// round 1
// baseline (speedup 1.0000x reference)
#include <cuda_runtime.h>
#include <math.h>

// Problem constants
#define BB    32
#define CIN   128
#define COUT  256
#define KK    16
#define LL    2048
#define HID   32
#define MAXK  24
#define PADC  12
#define LOUT  2049          // L + 2*PAD - MAXK + 1
#define NPAD  2176          // 17 * 128, padded t-dimension for GEMM tiles
#define KRED  2048          // CIN * KK

// ---------------- device scratch (no cudaMalloc allowed) ----------------
__device__ float g_y[(size_t)BB * KRED * NPAD];   // y[b][c*16+k][t], ~570 MB
__device__ float g_red[BB][HID];                  // partial relu-mean sums
__device__ int   g_cnt[BB][KK];                   // sparse tap counts per (b,k)
__device__ int   g_joff[BB][KK][48];              // tap j-offsets
__device__ float g_coef[BB][KK][48];              // tap coefficients

// ---------------- kernel 0: zero the reduction buffer -------------------
__global__ void k_zero_red() {
    g_red[blockIdx.x][threadIdx.x] = 0.f;
}

// ---------------- kernel 1: gate partial sums ----------------------------
// grid (32 batches, 4 l-chunks), 256 threads. Each thread handles 2 l's.
__global__ __launch_bounds__(256) void k_gate_partial(
    const float* __restrict__ x, const float* __restrict__ pred_w,
    const float* __restrict__ pred_b, const float* __restrict__ bn_gamma,
    const float* __restrict__ bn_beta, const float* __restrict__ bn_mean,
    const float* __restrict__ bn_var)
{
    int b = blockIdx.x, chunk = blockIdx.y;
    __shared__ float spw[HID * CIN];
    __shared__ float sscale[HID], sbias[HID];
    int tid = threadIdx.x;
    for (int i = tid; i < HID * CIN; i += 256) spw[i] = pred_w[i];
    if (tid < HID) {
        float sc = bn_gamma[tid] * rsqrtf(bn_var[tid] + 1e-5f);
        sscale[tid] = sc;
        sbias[tid]  = bn_beta[tid] + (pred_b[tid] - bn_mean[tid]) * sc;
    }
    __syncthreads();

    int l0 = chunk * 512 + tid;          // l0 and l0+256
    const float* xb = x + (size_t)b * CIN * LL;
    float acc0[HID], acc1[HID];
#pragma unroll
    for (int h = 0; h < HID; h++) { acc0[h] = 0.f; acc1[h] = 0.f; }
    for (int c = 0; c < CIN; c++) {
        float xv0 = xb[c * LL + l0];
        float xv1 = xb[c * LL + l0 + 256];
#pragma unroll
        for (int h = 0; h < HID; h++) {
            float w = spw[h * CIN + c];
            acc0[h] += w * xv0;
            acc1[h] += w * xv1;
        }
    }
    float msum[HID];
#pragma unroll
    for (int h = 0; h < HID; h++) {
        float z0 = fmaxf(acc0[h] * sscale[h] + sbias[h], 0.f);
        float z1 = fmaxf(acc1[h] * sscale[h] + sbias[h], 0.f);
        msum[h] = z0 + z1;
    }
    // warp reduce then atomic
#pragma unroll
    for (int h = 0; h < HID; h++) {
#pragma unroll
        for (int o = 16; o > 0; o >>= 1)
            msum[h] += __shfl_down_sync(0xffffffffu, msum[h], o);
    }
    if ((tid & 31) == 0) {
#pragma unroll
        for (int h = 0; h < HID; h++)
            atomicAdd(&g_red[b][h], msum[h]);
    }
}

// ---------------- kernel 2: finalize gate, build sparse tap lists --------
// grid 32 (one block per batch), 32 threads (one warp)
__global__ void k_finalize(const float* __restrict__ lin_w,
                           const float* __restrict__ lin_b)
{
    int b = blockIdx.x, h = threadIdx.x;
    float hm = g_red[b][h] * (1.f / 2048.f);
    float z = hm * lin_w[h];
#pragma unroll
    for (int o = 16; o > 0; o >>= 1)
        z += __shfl_down_sync(0xffffffffu, z, o);
    if (h == 0) {
        z += lin_b[0];
        float sig = 1.f / (1.f + expf(-z));
        float mult = 0.5f + sig;
        float ksz = fminf(fmaxf(rintf((float)KK * mult), 2.f), 3.f * (float)KK);
        int cnt[KK];
#pragma unroll
        for (int k = 0; k < KK; k++) cnt[k] = 0;
        float scale = ksz / (float)MAXK;
        for (int j = 0; j < MAXK; j++) {
            float tj = (j == MAXK - 1) ? 1.f : (-1.f + (float)j * (2.f / 23.f));
            float g = tj * scale;
            float p = (g + 1.f) * 0.5f * (float)(KK - 1);
            float fi = floorf(p);
            int i0 = (int)fminf(fmaxf(fi, 0.f), (float)(KK - 1));
            int i1 = min(i0 + 1, KK - 1);
            float w = p - (float)i0;
            int e0 = cnt[i0]++;
            g_joff[b][i0][e0] = j;  g_coef[b][i0][e0] = 1.f - w;
            int e1 = cnt[i1]++;
            g_joff[b][i1][e1] = j;  g_coef[b][i1][e1] = w;
        }
#pragma unroll
        for (int k = 0; k < KK; k++) g_cnt[b][k] = cnt[k];
    }
}

// ---------------- kernel 3: pass A — build y -----------------------------
// grid (CIN, B), 512 threads; warp w handles output index k=w for this (b,c).
__global__ __launch_bounds__(512) void k_passA(const float* __restrict__ x)
{
    int c = blockIdx.x, b = blockIdx.y;
    __shared__ float xs[16 + LL + 160];       // zero-padded halo, 2224 floats
    __shared__ int   s_jo[KK * 48];
    __shared__ float s_cf[KK * 48];
    __shared__ int   s_cnt[KK];
    int tid = threadIdx.x;

    for (int i = tid; i < 16 + LL + 160; i += 512) xs[i] = 0.f;
    for (int i = tid; i < KK * 48; i += 512) {
        s_jo[i] = (&g_joff[b][0][0])[i];
        s_cf[i] = (&g_coef[b][0][0])[i];
    }
    if (tid < KK) s_cnt[tid] = g_cnt[b][tid];
    __syncthreads();
    ((float4*)(xs + 16))[tid] =
        ((const float4*)(x + (size_t)(b * CIN + c) * LL))[tid];
    __syncthreads();

    int k = tid >> 5, lane = tid & 31;
    int cnt = s_cnt[k];
    float* yrow = g_y + ((size_t)b * KRED + c * KK + k) * NPAD;

    for (int pass = 0; pass < 17; pass++) {
        int t0 = pass * 128 + lane;
        float a0 = 0.f, a1 = 0.f, a2 = 0.f, a3 = 0.f;
        for (int e = 0; e < cnt; e++) {
            int   jo = s_jo[k * 48 + e];
            float cf = s_cf[k * 48 + e];
            const float* xp = xs + 4 + t0 + jo;   // 16 (base) - 12 (pad) = 4
            a0 += cf * xp[0];
            a1 += cf * xp[32];
            a2 += cf * xp[64];
            a3 += cf * xp[96];
        }
        int t;
        t = t0;      yrow[t] = (t < LOUT) ? a0 : 0.f;
        t = t0 + 32; yrow[t] = (t < LOUT) ? a1 : 0.f;
        t = t0 + 64; yrow[t] = (t < LOUT) ? a2 : 0.f;
        t = t0 + 96; yrow[t] = (t < LOUT) ? a3 : 0.f;
    }
}

// ---------------- kernel 4: pass B — batched GEMM ------------------------
// C_b[256 x 2049] = W[256 x 2048] @ Y_b[2048 x 2176(padded)]
// BM=128, BN=128, BK=16, 256 threads, 8x8 micro-tile.
__global__ __launch_bounds__(256) void k_gemm(const float* __restrict__ W,
                                              float* __restrict__ out)
{
    int nt = blockIdx.x, mt = blockIdx.y, b = blockIdx.z;
    const float* Y = g_y + (size_t)b * KRED * NPAD;

    __shared__ float As[16][132];   // padded stride, 528B row (16B aligned)
    __shared__ float Bs[16][128];

    int tid = threadIdx.x;
    int tx = tid & 15, ty = tid >> 4;
    int m0 = mt * 128, n0 = nt * 128;

    float acc[8][8];
#pragma unroll
    for (int i = 0; i < 8; i++)
#pragma unroll
        for (int j = 0; j < 8; j++) acc[i][j] = 0.f;

    int ar0 = tid >> 2, ac0 = (tid & 3) * 4;     // A: 2 rows (ar0, ar0+64)
    int br0 = tid >> 5, bc0 = (tid & 31) * 4;    // B: 2 rows (br0, br0+8)

    for (int k0 = 0; k0 < KRED; k0 += 16) {
        __syncthreads();
        float4 a4  = *(const float4*)&W[(size_t)(m0 + ar0) * KRED + k0 + ac0];
        float4 a4b = *(const float4*)&W[(size_t)(m0 + ar0 + 64) * KRED + k0 + ac0];
        As[ac0 + 0][ar0] = a4.x;  As[ac0 + 1][ar0] = a4.y;
        As[ac0 + 2][ar0] = a4.z;  As[ac0 + 3][ar0] = a4.w;
        As[ac0 + 0][ar0 + 64] = a4b.x;  As[ac0 + 1][ar0 + 64] = a4b.y;
        As[ac0 + 2][ar0 + 64] = a4b.z;  As[ac0 + 3][ar0 + 64] = a4b.w;
        float4 b4  = *(const float4*)&Y[(size_t)(k0 + br0) * NPAD + n0 + bc0];
        float4 b4b = *(const float4*)&Y[(size_t)(k0 + br0 + 8) * NPAD + n0 + bc0];
        *(float4*)&Bs[br0][bc0]     = b4;
        *(float4*)&Bs[br0 + 8][bc0] = b4b;
        __syncthreads();

#pragma unroll
        for (int k = 0; k < 16; k++) {
            float ar[8], br[8];
            *(float4*)(ar)     = *(const float4*)&As[k][ty * 8];
            *(float4*)(ar + 4) = *(const float4*)&As[k][ty * 8 + 4];
            *(float4*)(br)     = *(const float4*)&Bs[k][tx * 8];
            *(float4*)(br + 4) = *(const float4*)&Bs[k][tx * 8 + 4];
#pragma unroll
            for (int i = 0; i < 8; i++)
#pragma unroll
                for (int j = 0; j < 8; j++)
                    acc[i][j] += ar[i] * br[j];
        }
    }

#pragma unroll
    for (int i = 0; i < 8; i++) {
        int m = m0 + ty * 8 + i;
#pragma unroll
        for (int j = 0; j < 8; j++) {
            int n = n0 + tx * 8 + j;
            if (n < LOUT)
                out[((size_t)b * COUT + m) * LOUT + n] = acc[i][j];
        }
    }
}

// ---------------- launcher ----------------------------------------------
extern "C" void kernel_launch(void* const* d_in, const int* in_sizes, int n_in,
                              void* d_out, int out_size)
{
    (void)in_sizes; (void)n_in; (void)out_size;
    const float* x        = (const float*)d_in[0];
    const float* base_w   = (const float*)d_in[1];
    const float* pred_w   = (const float*)d_in[2];
    const float* pred_b   = (const float*)d_in[3];
    const float* bn_gamma = (const float*)d_in[4];
    const float* bn_beta  = (const float*)d_in[5];
    const float* bn_mean  = (const float*)d_in[6];
    const float* bn_var   = (const float*)d_in[7];
    const float* lin_w    = (const float*)d_in[8];
    const float* lin_b    = (const float*)d_in[9];
    float* out = (float*)d_out;

    k_zero_red<<<BB, HID>>>();
    k_gate_partial<<<dim3(BB, 4), 256>>>(x, pred_w, pred_b, bn_gamma,
                                         bn_beta, bn_mean, bn_var);
    k_finalize<<<BB, HID>>>(lin_w, lin_b);
    k_passA<<<dim3(CIN, BB), 512>>>(x);
    k_gemm<<<dim3(17, 2, BB), 256>>>(base_w, out);
}

// round 4
// speedup vs baseline: 2.4463x; 2.4463x over previous
#include <cuda_runtime.h>
#include <cuda_fp16.h>
#include <math.h>
#include <stdint.h>

// Problem constants
#define BB    32
#define CIN   128
#define COUT  256
#define KK    16
#define LL    2048
#define HID   32
#define MAXK  24
#define LOUT  2049          // L + 2*12 - 24 + 1
#define TPAD  2176          // 17 * 128 padded t-dimension
#define KRED  2048          // CIN * KK

// ---------------- device scratch (no cudaMalloc allowed) ----------------
__device__ __half g_wh[COUT * KRED];                 // W hi (fp16)
__device__ __half g_wl[COUT * KRED];                 // W lo residual (fp16)
__device__ __half g_yh[(size_t)BB * TPAD * KRED];    // y[b][t][k] fp16, 285 MB
__device__ float g_red[BB][HID];
__device__ int   g_cnt[BB][KK];
__device__ int   g_joff[BB][KK][48];
__device__ float g_coef[BB][KK][48];

// ---------------- kernel 0: zero the reduction buffer -------------------
__global__ void k_zero_red() {
    g_red[blockIdx.x][threadIdx.x] = 0.f;
}

// ---------------- kernel 1: gate partial sums ----------------------------
__global__ __launch_bounds__(256) void k_gate_partial(
    const float* __restrict__ x, const float* __restrict__ pred_w,
    const float* __restrict__ pred_b, const float* __restrict__ bn_gamma,
    const float* __restrict__ bn_beta, const float* __restrict__ bn_mean,
    const float* __restrict__ bn_var)
{
    int b = blockIdx.x, chunk = blockIdx.y;
    __shared__ float spw[HID * CIN];
    __shared__ float sscale[HID], sbias[HID];
    int tid = threadIdx.x;
    for (int i = tid; i < HID * CIN; i += 256) spw[i] = pred_w[i];
    if (tid < HID) {
        float sc = bn_gamma[tid] * rsqrtf(bn_var[tid] + 1e-5f);
        sscale[tid] = sc;
        sbias[tid]  = bn_beta[tid] + (pred_b[tid] - bn_mean[tid]) * sc;
    }
    __syncthreads();

    int l0 = chunk * 512 + tid;
    const float* xb = x + (size_t)b * CIN * LL;
    float acc0[HID], acc1[HID];
#pragma unroll
    for (int h = 0; h < HID; h++) { acc0[h] = 0.f; acc1[h] = 0.f; }
    for (int c = 0; c < CIN; c++) {
        float xv0 = xb[c * LL + l0];
        float xv1 = xb[c * LL + l0 + 256];
#pragma unroll
        for (int h = 0; h < HID; h++) {
            float w = spw[h * CIN + c];
            acc0[h] += w * xv0;
            acc1[h] += w * xv1;
        }
    }
    float msum[HID];
#pragma unroll
    for (int h = 0; h < HID; h++) {
        float z0 = fmaxf(acc0[h] * sscale[h] + sbias[h], 0.f);
        float z1 = fmaxf(acc1[h] * sscale[h] + sbias[h], 0.f);
        msum[h] = z0 + z1;
    }
#pragma unroll
    for (int h = 0; h < HID; h++) {
#pragma unroll
        for (int o = 16; o > 0; o >>= 1)
            msum[h] += __shfl_down_sync(0xffffffffu, msum[h], o);
    }
    if ((tid & 31) == 0) {
#pragma unroll
        for (int h = 0; h < HID; h++)
            atomicAdd(&g_red[b][h], msum[h]);
    }
}

// ---------------- kernel 2: finalize gate, build sparse tap lists --------
__global__ void k_finalize(const float* __restrict__ lin_w,
                           const float* __restrict__ lin_b)
{
    int b = blockIdx.x, h = threadIdx.x;
    float hm = g_red[b][h] * (1.f / 2048.f);
    float z = hm * lin_w[h];
#pragma unroll
    for (int o = 16; o > 0; o >>= 1)
        z += __shfl_down_sync(0xffffffffu, z, o);
    if (h == 0) {
        z += lin_b[0];
        float sig = 1.f / (1.f + expf(-z));
        float mult = 0.5f + sig;
        float ksz = fminf(fmaxf(rintf((float)KK * mult), 2.f), 3.f * (float)KK);
        int cnt[KK];
#pragma unroll
        for (int k = 0; k < KK; k++) cnt[k] = 0;
        float scale = ksz / (float)MAXK;
        for (int j = 0; j < MAXK; j++) {
            float tj = (j == MAXK - 1) ? 1.f : (-1.f + (float)j * (2.f / 23.f));
            float g = tj * scale;
            float p = (g + 1.f) * 0.5f * (float)(KK - 1);
            float fi = floorf(p);
            int i0 = (int)fminf(fmaxf(fi, 0.f), (float)(KK - 1));
            int i1 = min(i0 + 1, KK - 1);
            float w = p - (float)i0;
            int e0 = cnt[i0]++;
            g_joff[b][i0][e0] = j;  g_coef[b][i0][e0] = 1.f - w;
            int e1 = cnt[i1]++;
            g_joff[b][i1][e1] = j;  g_coef[b][i1][e1] = w;
        }
#pragma unroll
        for (int k = 0; k < KK; k++) g_cnt[b][k] = cnt[k];
    }
}

// ---------------- kernel 2b: split W into fp16 hi/lo ---------------------
__global__ __launch_bounds__(256) void k_wsplit(const float* __restrict__ W)
{
    int i = blockIdx.x * 256 + threadIdx.x;   // 2048 * 256 = 524288
    float w = W[i];
    __half h = __float2half_rn(w);
    g_wh[i] = h;
    g_wl[i] = __float2half_rn(w - __half2float(h));
}

// ---------------- kernel 3: pass A — build y[b][t][k] (fp16) -------------
__global__ __launch_bounds__(256) void k_passA_T(const float* __restrict__ x)
{
    extern __shared__ float xs[];            // CIN * 152 floats = 77824 B
    __shared__ int   s_jo[KK * 48];
    __shared__ float s_cf[KK * 48];
    __shared__ int   s_cnt[KK];
    int tchunk = blockIdx.x, b = blockIdx.y;
    int t0 = tchunk * 128;
    int tid = threadIdx.x;

    for (int i = tid; i < KK * 48; i += 256) {
        s_jo[i] = (&g_joff[b][0][0])[i];
        s_cf[i] = (&g_coef[b][0][0])[i];
    }
    if (tid < KK) s_cnt[tid] = g_cnt[b][tid];

    const float* xb = x + (size_t)b * CIN * LL;
    for (int i = tid; i < CIN * 152; i += 256) {
        int c = i / 152, dl = i - c * 152;
        int l = t0 - 12 + dl;
        xs[i] = (l >= 0 && l < LL) ? xb[c * LL + l] : 0.f;
    }
    __syncthreads();

    for (int g = 0; g < 4; g++) {
        int ck = (tid + 256 * g) * 2;        // even ck
        int c = ck >> 4, k = ck & 15;        // pair (k, k+1)
        int cnt0 = s_cnt[k], cnt1 = s_cnt[k + 1];
        const float* xr = xs + c * 152;
        __half* ybase = g_yh + (size_t)b * TPAD * KRED + ck;

        for (int tc = 0; tc < 16; tc++) {
            float y0[8], y1[8];
#pragma unroll
            for (int u = 0; u < 8; u++) { y0[u] = 0.f; y1[u] = 0.f; }
            int tb = tc * 8;
            for (int e = 0; e < cnt0; e++) {
                float cf = s_cf[k * 48 + e];
                const float* xp = xr + tb + s_jo[k * 48 + e];
#pragma unroll
                for (int u = 0; u < 8; u++) y0[u] += cf * xp[u];
            }
            for (int e = 0; e < cnt1; e++) {
                float cf = s_cf[(k + 1) * 48 + e];
                const float* xp = xr + tb + s_jo[(k + 1) * 48 + e];
#pragma unroll
                for (int u = 0; u < 8; u++) y1[u] += cf * xp[u];
            }
#pragma unroll
            for (int u = 0; u < 8; u++) {
                int t = t0 + tb + u;
                __half2 v;
                v.x = __float2half_rn(y0[u]);
                v.y = __float2half_rn(y1[u]);
                *(__half2*)(ybase + (size_t)t * KRED) = v;
            }
        }
    }
}

// ---------------- HMMA helpers -------------------------------------------
__device__ __forceinline__ uint32_t s2u(const void* p) {
    uint32_t a;
    asm("{ .reg .u64 t; cvta.to.shared.u64 t, %1; cvt.u32.u64 %0, t; }"
        : "=r"(a) : "l"(p));
    return a;
}
__device__ __forceinline__ void cpa16(uint32_t dst, const void* src) {
    asm volatile("cp.async.cg.shared.global [%0], [%1], 16;"
                 :: "r"(dst), "l"(src));
}
__device__ __forceinline__ void ldsm4(uint32_t* r, uint32_t addr) {
    asm volatile("ldmatrix.sync.aligned.m8n8.x4.shared.b16 {%0,%1,%2,%3}, [%4];"
                 : "=r"(r[0]), "=r"(r[1]), "=r"(r[2]), "=r"(r[3]) : "r"(addr));
}
__device__ __forceinline__ void mma16816(float* c, const uint32_t* a,
                                         const uint32_t* b) {
    asm volatile(
        "mma.sync.aligned.m16n8k16.row.col.f32.f16.f16.f32 "
        "{%0,%1,%2,%3}, {%4,%5,%6,%7}, {%8,%9}, {%0,%1,%2,%3};"
        : "+f"(c[0]), "+f"(c[1]), "+f"(c[2]), "+f"(c[3])
        : "r"(a[0]), "r"(a[1]), "r"(a[2]), "r"(a[3]), "r"(b[0]), "r"(b[1]));
}
__device__ __forceinline__ uint32_t sw(uint32_t off) {
    return off ^ ((off >> 3) & 0x70);
}

#define STAGE_BYTES 49152                 // Ahi 16K + Alo 16K + B 16K (BK=64)
#define GEMM_DYN    (2 * STAGE_BYTES + 1024)

__device__ __forceinline__ void load_chunk(int ci, int s, int tid, uint32_t dynb,
    const __half* A_h, const __half* A_l, const __half* B_h)
{
    uint32_t sb = dynb + s * STAGE_BYTES;
    int k0 = ci * 64;
#pragma unroll
    for (int it = 0; it < 12; it++) {
        int tile = it >> 2;
        int within = ((it & 3) << 8) + tid;
        int row = within >> 3, c16 = within & 7;
        const __half* src = (tile == 0 ? A_h : tile == 1 ? A_l : B_h)
                            + (size_t)row * KRED + k0 + c16 * 8;
        uint32_t off = row * 128 + c16 * 16;
        cpa16(sb + tile * 16384 + sw(off), src);
    }
    asm volatile("cp.async.commit_group;" ::: "memory");
}

// ---------------- kernel 4: HMMA GEMM ------------------------------------
// C_b[m0:+128, n0:+128] = (Whi + Wlo)[128,2048] @ Y_b[n0:+128, 2048]^T
__global__ __launch_bounds__(256) void k_gemm_mma(float* __restrict__ out)
{
    extern __shared__ __align__(16) char dynraw[];
    char* dynp = (char*)(((size_t)dynraw + 1023) & ~(size_t)1023);
    uint32_t dynb = s2u(dynp);
    int tid = threadIdx.x, wid = tid >> 5, lid = tid & 31;
    int nt = blockIdx.x, mt = blockIdx.y, b = blockIdx.z;
    int warp_m = wid & 3, warp_n = wid >> 2;       // 4 x 2 warps

    const __half* A_h = g_wh + (size_t)mt * 128 * KRED;
    const __half* A_l = g_wl + (size_t)mt * 128 * KRED;
    const __half* B_h = g_yh + ((size_t)b * TPAD + nt * 128) * KRED;

    float acc[2][8][4];
#pragma unroll
    for (int i = 0; i < 2; i++)
#pragma unroll
        for (int j = 0; j < 8; j++)
#pragma unroll
            for (int v = 0; v < 4; v++) acc[i][j][v] = 0.f;

    load_chunk(0, 0, tid, dynb, A_h, A_l, B_h);
    load_chunk(1, 1, tid, dynb, A_h, A_l, B_h);

    // precomputed intra-warp ldmatrix offsets (row, colbyte parts)
    int a_row = warp_m * 32 + (lid & 15);          // + mtile*16
    int a_cb  = (lid >> 4) * 16;
    int b_row = warp_n * 64 + (lid & 7) + ((lid >> 4) << 3);  // + nb*16
    int b_cb  = ((lid >> 3) & 1) * 16;

    for (int ci = 0; ci < 32; ci++) {
        int s = ci & 1;
        asm volatile("cp.async.wait_group 1;" ::: "memory");
        __syncthreads();
        uint32_t sa_h = dynb + s * STAGE_BYTES;
        uint32_t sa_l = sa_h + 16384;
        uint32_t sbb  = sa_h + 32768;

#pragma unroll
        for (int ks = 0; ks < 4; ks++) {
            int kbyte = ks * 32;
            uint32_t ah[2][4], al[2][4], bf[4][4];
#pragma unroll
            for (int mtile = 0; mtile < 2; mtile++) {
                uint32_t off = (a_row + mtile * 16) * 128 + kbyte + a_cb;
                ldsm4(ah[mtile], sa_h + sw(off));
                ldsm4(al[mtile], sa_l + sw(off));
            }
#pragma unroll
            for (int nb = 0; nb < 4; nb++) {
                uint32_t off = (b_row + nb * 16) * 128 + kbyte + b_cb;
                ldsm4(bf[nb], sbb + sw(off));
            }
#pragma unroll
            for (int mtile = 0; mtile < 2; mtile++)
#pragma unroll
                for (int nb = 0; nb < 4; nb++) {
#pragma unroll
                    for (int hh = 0; hh < 2; hh++) {
                        mma16816(acc[mtile][nb * 2 + hh], ah[mtile],
                                 &bf[nb][hh * 2]);
                        mma16816(acc[mtile][nb * 2 + hh], al[mtile],
                                 &bf[nb][hh * 2]);
                    }
                }
        }
        __syncthreads();
        if (ci + 2 < 32) load_chunk(ci + 2, s, tid, dynb, A_h, A_l, B_h);
    }

    // ------- epilogue: scalar stores (LOUT=2049 is odd; float2 would
    //         be misaligned for odd m). Quad pattern still fills 32B
    //         sectors per 4 lanes. ---------------------------------------
    int n0 = nt * 128;
    int qrow = lid >> 2, qcol = (lid & 3) * 2;
    size_t ob = ((size_t)b * COUT + mt * 128 + warp_m * 32) * LOUT;
#pragma unroll
    for (int mtile = 0; mtile < 2; mtile++) {
#pragma unroll
        for (int n8 = 0; n8 < 8; n8++) {
            int n = n0 + warp_n * 64 + n8 * 8 + qcol;
#pragma unroll
            for (int half = 0; half < 2; half++) {
                int m = mtile * 16 + half * 8 + qrow;
                float* dst = out + ob + (size_t)m * LOUT + n;
                float v0 = acc[mtile][n8][half * 2];
                float v1 = acc[mtile][n8][half * 2 + 1];
                if (n < LOUT)     dst[0] = v0;
                if (n + 1 < LOUT) dst[1] = v1;
            }
        }
    }
}

// ---------------- launcher ----------------------------------------------
extern "C" void kernel_launch(void* const* d_in, const int* in_sizes, int n_in,
                              void* d_out, int out_size)
{
    (void)in_sizes; (void)n_in; (void)out_size;
    const float* x        = (const float*)d_in[0];
    const float* base_w   = (const float*)d_in[1];
    const float* pred_w   = (const float*)d_in[2];
    const float* pred_b   = (const float*)d_in[3];
    const float* bn_gamma = (const float*)d_in[4];
    const float* bn_beta  = (const float*)d_in[5];
    const float* bn_mean  = (const float*)d_in[6];
    const float* bn_var   = (const float*)d_in[7];
    const float* lin_w    = (const float*)d_in[8];
    const float* lin_b    = (const float*)d_in[9];
    float* out = (float*)d_out;

    cudaFuncSetAttribute(k_passA_T,
        cudaFuncAttributeMaxDynamicSharedMemorySize, CIN * 152 * 4);
    cudaFuncSetAttribute(k_gemm_mma,
        cudaFuncAttributeMaxDynamicSharedMemorySize, GEMM_DYN);

    k_zero_red<<<BB, HID>>>();
    k_gate_partial<<<dim3(BB, 4), 256>>>(x, pred_w, pred_b, bn_gamma,
                                         bn_beta, bn_mean, bn_var);
    k_finalize<<<BB, HID>>>(lin_w, lin_b);
    k_wsplit<<<2048, 256>>>(base_w);
    k_passA_T<<<dim3(17, BB), 256, CIN * 152 * 4>>>(x);
    k_gemm_mma<<<dim3(17, 2, BB), 256, GEMM_DYN>>>(out);
}

// round 5
// speedup vs baseline: 3.3013x; 1.3495x over previous
#include <cuda_runtime.h>
#include <cuda_fp16.h>
#include <math.h>
#include <stdint.h>

// Problem constants
#define BB    32
#define CIN   128
#define COUT  256
#define KK    16
#define LL    2048
#define HID   32
#define MAXK  24
#define LOUT  2049          // L + 2*12 - 24 + 1
#define TPAD  2176          // 17 * 128 padded t-dimension
#define KRED  2048          // CIN * KK

// ---------------- device scratch (no cudaMalloc allowed) ----------------
__device__ __half g_wh[COUT * KRED];                 // W (fp16)
__device__ __half g_yh[(size_t)BB * TPAD * KRED];    // y[b][t][k] fp16, 285 MB
__device__ float g_red[BB][HID];
__device__ int   g_cnt[BB][KK];
__device__ int   g_joff[BB][KK][48];
__device__ float g_coef[BB][KK][48];

// ---------------- kernel 0: zero the reduction buffer -------------------
__global__ void k_zero_red() {
    g_red[blockIdx.x][threadIdx.x] = 0.f;
}

// ---------------- kernel 1: gate partial sums ----------------------------
__global__ __launch_bounds__(256) void k_gate_partial(
    const float* __restrict__ x, const float* __restrict__ pred_w,
    const float* __restrict__ pred_b, const float* __restrict__ bn_gamma,
    const float* __restrict__ bn_beta, const float* __restrict__ bn_mean,
    const float* __restrict__ bn_var)
{
    int b = blockIdx.x, chunk = blockIdx.y;
    __shared__ float spw[HID * CIN];
    __shared__ float sscale[HID], sbias[HID];
    int tid = threadIdx.x;
    for (int i = tid; i < HID * CIN; i += 256) spw[i] = pred_w[i];
    if (tid < HID) {
        float sc = bn_gamma[tid] * rsqrtf(bn_var[tid] + 1e-5f);
        sscale[tid] = sc;
        sbias[tid]  = bn_beta[tid] + (pred_b[tid] - bn_mean[tid]) * sc;
    }
    __syncthreads();

    int l0 = chunk * 512 + tid;
    const float* xb = x + (size_t)b * CIN * LL;
    float acc0[HID], acc1[HID];
#pragma unroll
    for (int h = 0; h < HID; h++) { acc0[h] = 0.f; acc1[h] = 0.f; }
    for (int c = 0; c < CIN; c++) {
        float xv0 = xb[c * LL + l0];
        float xv1 = xb[c * LL + l0 + 256];
#pragma unroll
        for (int h = 0; h < HID; h++) {
            float w = spw[h * CIN + c];
            acc0[h] += w * xv0;
            acc1[h] += w * xv1;
        }
    }
    float msum[HID];
#pragma unroll
    for (int h = 0; h < HID; h++) {
        float z0 = fmaxf(acc0[h] * sscale[h] + sbias[h], 0.f);
        float z1 = fmaxf(acc1[h] * sscale[h] + sbias[h], 0.f);
        msum[h] = z0 + z1;
    }
#pragma unroll
    for (int h = 0; h < HID; h++) {
#pragma unroll
        for (int o = 16; o > 0; o >>= 1)
            msum[h] += __shfl_down_sync(0xffffffffu, msum[h], o);
    }
    if ((tid & 31) == 0) {
#pragma unroll
        for (int h = 0; h < HID; h++)
            atomicAdd(&g_red[b][h], msum[h]);
    }
}

// ---------------- kernel 2: finalize gate, build sparse tap lists --------
__global__ void k_finalize(const float* __restrict__ lin_w,
                           const float* __restrict__ lin_b)
{
    int b = blockIdx.x, h = threadIdx.x;
    float hm = g_red[b][h] * (1.f / 2048.f);
    float z = hm * lin_w[h];
#pragma unroll
    for (int o = 16; o > 0; o >>= 1)
        z += __shfl_down_sync(0xffffffffu, z, o);
    if (h == 0) {
        z += lin_b[0];
        float sig = 1.f / (1.f + expf(-z));
        float mult = 0.5f + sig;
        float ksz = fminf(fmaxf(rintf((float)KK * mult), 2.f), 3.f * (float)KK);
        int cnt[KK];
#pragma unroll
        for (int k = 0; k < KK; k++) cnt[k] = 0;
        float scale = ksz / (float)MAXK;
        for (int j = 0; j < MAXK; j++) {
            float tj = (j == MAXK - 1) ? 1.f : (-1.f + (float)j * (2.f / 23.f));
            float g = tj * scale;
            float p = (g + 1.f) * 0.5f * (float)(KK - 1);
            float fi = floorf(p);
            int i0 = (int)fminf(fmaxf(fi, 0.f), (float)(KK - 1));
            int i1 = min(i0 + 1, KK - 1);
            float w = p - (float)i0;
            int e0 = cnt[i0]++;
            g_joff[b][i0][e0] = j;  g_coef[b][i0][e0] = 1.f - w;
            int e1 = cnt[i1]++;
            g_joff[b][i1][e1] = j;  g_coef[b][i1][e1] = w;
        }
#pragma unroll
        for (int k = 0; k < KK; k++) g_cnt[b][k] = cnt[k];
    }
}

// ---------------- kernel 2b: W -> fp16 -----------------------------------
__global__ __launch_bounds__(256) void k_wsplit(const float* __restrict__ W)
{
    int i = blockIdx.x * 256 + threadIdx.x;   // 2048 * 256 = 524288
    g_wh[i] = __float2half_rn(W[i]);
}

// ---------------- kernel 3: pass A — build y[b][t][k] (fp16) -------------
__global__ __launch_bounds__(256) void k_passA_T(const float* __restrict__ x)
{
    extern __shared__ float xs[];            // CIN * 152 floats = 77824 B
    __shared__ int   s_jo[KK * 48];
    __shared__ float s_cf[KK * 48];
    __shared__ int   s_cnt[KK];
    int tchunk = blockIdx.x, b = blockIdx.y;
    int t0 = tchunk * 128;
    int tid = threadIdx.x;

    for (int i = tid; i < KK * 48; i += 256) {
        s_jo[i] = (&g_joff[b][0][0])[i];
        s_cf[i] = (&g_coef[b][0][0])[i];
    }
    if (tid < KK) s_cnt[tid] = g_cnt[b][tid];

    const float* xb = x + (size_t)b * CIN * LL;
    for (int i = tid; i < CIN * 152; i += 256) {
        int c = i / 152, dl = i - c * 152;
        int l = t0 - 12 + dl;
        xs[i] = (l >= 0 && l < LL) ? xb[c * LL + l] : 0.f;
    }
    __syncthreads();

    for (int g = 0; g < 4; g++) {
        int ck = (tid + 256 * g) * 2;        // even ck
        int c = ck >> 4, k = ck & 15;        // pair (k, k+1)
        int cnt0 = s_cnt[k], cnt1 = s_cnt[k + 1];
        const float* xr = xs + c * 152;
        __half* ybase = g_yh + (size_t)b * TPAD * KRED + ck;

        for (int tc = 0; tc < 16; tc++) {
            float y0[8], y1[8];
#pragma unroll
            for (int u = 0; u < 8; u++) { y0[u] = 0.f; y1[u] = 0.f; }
            int tb = tc * 8;
            for (int e = 0; e < cnt0; e++) {
                float cf = s_cf[k * 48 + e];
                const float* xp = xr + tb + s_jo[k * 48 + e];
#pragma unroll
                for (int u = 0; u < 8; u++) y0[u] += cf * xp[u];
            }
            for (int e = 0; e < cnt1; e++) {
                float cf = s_cf[(k + 1) * 48 + e];
                const float* xp = xr + tb + s_jo[(k + 1) * 48 + e];
#pragma unroll
                for (int u = 0; u < 8; u++) y1[u] += cf * xp[u];
            }
#pragma unroll
            for (int u = 0; u < 8; u++) {
                int t = t0 + tb + u;
                __half2 v;
                v.x = __float2half_rn(y0[u]);
                v.y = __float2half_rn(y1[u]);
                *(__half2*)(ybase + (size_t)t * KRED) = v;
            }
        }
    }
}

// ---------------- HMMA helpers -------------------------------------------
__device__ __forceinline__ uint32_t s2u(const void* p) {
    uint32_t a;
    asm("{ .reg .u64 t; cvta.to.shared.u64 t, %1; cvt.u32.u64 %0, t; }"
        : "=r"(a) : "l"(p));
    return a;
}
__device__ __forceinline__ void cpa16(uint32_t dst, const void* src) {
    asm volatile("cp.async.cg.shared.global [%0], [%1], 16;"
                 :: "r"(dst), "l"(src));
}
__device__ __forceinline__ void ldsm4(uint32_t* r, uint32_t addr) {
    asm volatile("ldmatrix.sync.aligned.m8n8.x4.shared.b16 {%0,%1,%2,%3}, [%4];"
                 : "=r"(r[0]), "=r"(r[1]), "=r"(r[2]), "=r"(r[3]) : "r"(addr));
}
__device__ __forceinline__ void mma16816(float* c, const uint32_t* a,
                                         const uint32_t* b) {
    asm volatile(
        "mma.sync.aligned.m16n8k16.row.col.f32.f16.f16.f32 "
        "{%0,%1,%2,%3}, {%4,%5,%6,%7}, {%8,%9}, {%0,%1,%2,%3};"
        : "+f"(c[0]), "+f"(c[1]), "+f"(c[2]), "+f"(c[3])
        : "r"(a[0]), "r"(a[1]), "r"(a[2]), "r"(a[3]), "r"(b[0]), "r"(b[1]));
}
__device__ __forceinline__ uint32_t sw(uint32_t off) {
    return off ^ ((off >> 3) & 0x70);
}

#define STAGE_BYTES 32768                 // A 16K + B 16K (BK=64)
#define NSTAGE      3
#define GEMM_DYN    (NSTAGE * STAGE_BYTES + 1024)

__device__ __forceinline__ void load_chunk(int ci, int s, int tid, uint32_t dynb,
    const __half* A_h, const __half* B_h)
{
    uint32_t sb = dynb + s * STAGE_BYTES;
    int k0 = ci * 64;
#pragma unroll
    for (int it = 0; it < 8; it++) {
        int tile = it >> 2;
        int within = ((it & 3) << 8) + tid;
        int row = within >> 3, c16 = within & 7;
        const __half* src = (tile == 0 ? A_h : B_h)
                            + (size_t)row * KRED + k0 + c16 * 8;
        uint32_t off = row * 128 + c16 * 16;
        cpa16(sb + tile * 16384 + sw(off), src);
    }
    asm volatile("cp.async.commit_group;" ::: "memory");
}

// ---------------- kernel 4: HMMA GEMM ------------------------------------
// C_b[m0:+128, n0:+128] = W[128,2048] @ Y_b[n0:+128, 2048]^T
__global__ __launch_bounds__(256) void k_gemm_mma(float* __restrict__ out)
{
    extern __shared__ __align__(16) char dynraw[];
    char* dynp = (char*)(((size_t)dynraw + 1023) & ~(size_t)1023);
    uint32_t dynb = s2u(dynp);
    int tid = threadIdx.x, wid = tid >> 5, lid = tid & 31;
    int nt = blockIdx.x, mt = blockIdx.y, b = blockIdx.z;
    int warp_m = wid & 3, warp_n = wid >> 2;       // 4 x 2 warps

    const __half* A_h = g_wh + (size_t)mt * 128 * KRED;
    const __half* B_h = g_yh + ((size_t)b * TPAD + nt * 128) * KRED;

    float acc[2][8][4];
#pragma unroll
    for (int i = 0; i < 2; i++)
#pragma unroll
        for (int j = 0; j < 8; j++)
#pragma unroll
            for (int v = 0; v < 4; v++) acc[i][j][v] = 0.f;

    load_chunk(0, 0, tid, dynb, A_h, B_h);
    load_chunk(1, 1, tid, dynb, A_h, B_h);
    load_chunk(2, 2, tid, dynb, A_h, B_h);

    // intra-warp ldmatrix offsets
    int a_row = warp_m * 32 + (lid & 15);          // + mtile*16
    int a_cb  = (lid >> 4) * 16;
    int b_row = warp_n * 64 + (lid & 7) + ((lid >> 4) << 3);  // + nb*16
    int b_cb  = ((lid >> 3) & 1) * 16;

    int s = 0;
    for (int ci = 0; ci < 32; ci++) {
        if (ci < 30)       asm volatile("cp.async.wait_group 2;" ::: "memory");
        else if (ci == 30) asm volatile("cp.async.wait_group 1;" ::: "memory");
        else               asm volatile("cp.async.wait_group 0;" ::: "memory");
        __syncthreads();
        uint32_t sa  = dynb + s * STAGE_BYTES;
        uint32_t sbb = sa + 16384;

#pragma unroll
        for (int ks = 0; ks < 4; ks++) {
            int kbyte = ks * 32;
            uint32_t ah[2][4], bf[4][4];
#pragma unroll
            for (int mtile = 0; mtile < 2; mtile++) {
                uint32_t off = (a_row + mtile * 16) * 128 + kbyte + a_cb;
                ldsm4(ah[mtile], sa + sw(off));
            }
#pragma unroll
            for (int nb = 0; nb < 4; nb++) {
                uint32_t off = (b_row + nb * 16) * 128 + kbyte + b_cb;
                ldsm4(bf[nb], sbb + sw(off));
            }
#pragma unroll
            for (int mtile = 0; mtile < 2; mtile++)
#pragma unroll
                for (int nb = 0; nb < 4; nb++) {
#pragma unroll
                    for (int hh = 0; hh < 2; hh++)
                        mma16816(acc[mtile][nb * 2 + hh], ah[mtile],
                                 &bf[nb][hh * 2]);
                }
        }
        __syncthreads();
        if (ci + NSTAGE < 32) load_chunk(ci + NSTAGE, s, tid, dynb, A_h, B_h);
        s = (s == NSTAGE - 1) ? 0 : s + 1;
    }

    // ------- epilogue: scalar stores (LOUT odd => no vector stores) ------
    int n0 = nt * 128;
    int qrow = lid >> 2, qcol = (lid & 3) * 2;
    size_t ob = ((size_t)b * COUT + mt * 128 + warp_m * 32) * LOUT;
#pragma unroll
    for (int mtile = 0; mtile < 2; mtile++) {
#pragma unroll
        for (int n8 = 0; n8 < 8; n8++) {
            int n = n0 + warp_n * 64 + n8 * 8 + qcol;
#pragma unroll
            for (int half = 0; half < 2; half++) {
                int m = mtile * 16 + half * 8 + qrow;
                float* dst = out + ob + (size_t)m * LOUT + n;
                float v0 = acc[mtile][n8][half * 2];
                float v1 = acc[mtile][n8][half * 2 + 1];
                if (n < LOUT)     dst[0] = v0;
                if (n + 1 < LOUT) dst[1] = v1;
            }
        }
    }
}

// ---------------- launcher ----------------------------------------------
extern "C" void kernel_launch(void* const* d_in, const int* in_sizes, int n_in,
                              void* d_out, int out_size)
{
    (void)in_sizes; (void)n_in; (void)out_size;
    const float* x        = (const float*)d_in[0];
    const float* base_w   = (const float*)d_in[1];
    const float* pred_w   = (const float*)d_in[2];
    const float* pred_b   = (const float*)d_in[3];
    const float* bn_gamma = (const float*)d_in[4];
    const float* bn_beta  = (const float*)d_in[5];
    const float* bn_mean  = (const float*)d_in[6];
    const float* bn_var   = (const float*)d_in[7];
    const float* lin_w    = (const float*)d_in[8];
    const float* lin_b    = (const float*)d_in[9];
    float* out = (float*)d_out;

    cudaFuncSetAttribute(k_passA_T,
        cudaFuncAttributeMaxDynamicSharedMemorySize, CIN * 152 * 4);
    cudaFuncSetAttribute(k_gemm_mma,
        cudaFuncAttributeMaxDynamicSharedMemorySize, GEMM_DYN);

    k_zero_red<<<BB, HID>>>();
    k_gate_partial<<<dim3(BB, 4), 256>>>(x, pred_w, pred_b, bn_gamma,
                                         bn_beta, bn_mean, bn_var);
    k_finalize<<<BB, HID>>>(lin_w, lin_b);
    k_wsplit<<<2048, 256>>>(base_w);
    k_passA_T<<<dim3(17, BB), 256, CIN * 152 * 4>>>(x);
    k_gemm_mma<<<dim3(17, 2, BB), 256, GEMM_DYN>>>(out);
}